// round 16
// baseline (speedup 1.0000x reference)
#include <cuda_runtime.h>
#include <cuda_fp16.h>
#include <cstdint>

#define HD 128
#define SEQ 2048
#define NBH 32
#define BM 128
#define BN 64
#define NT (SEQ / BN)            // 32 key tiles
// Q scaled by (1/sqrt(128)) * log2(e) at smem-fill so softmax is exp2(sacc)
#define QKSCALE 0.12751581666519787f

// ---- fp16 scratch for K,V (filled by pre-pass kernel) ----
__device__ __align__(256) __half g_Kh[NBH * SEQ * HD];
__device__ __align__(256) __half g_Vh[NBH * SEQ * HD];

// smem strides in halves; 136 halves = 272B -> ldmatrix banks 4L..4L+3, conflict-free
#define QSTRH 136
#define KSTRH 136

// smem half-offsets: Q tile, then K double-buffer, then V double-buffer
#define SM_Q  0
#define SM_K0 (BM * QSTRH)
#define SM_K1 (SM_K0 + BN * KSTRH)
#define SM_V0 (SM_K1 + BN * KSTRH)
#define SM_V1 (SM_V0 + BN * KSTRH)
#define SMEM_HALVES (SM_V1 + BN * KSTRH)   // 52224 halves
#define SMEM_BYTES (SMEM_HALVES * 2)       // 104448 B -> 2 CTAs/SM

__device__ __forceinline__ uint32_t h2bits(__half2 h) {
    return *reinterpret_cast<uint32_t*>(&h);
}
__device__ __forceinline__ __half2 bitsh2(uint32_t u) {
    return *reinterpret_cast<__half2*>(&u);
}
__device__ __forceinline__ void mma16(float* d, const uint32_t* a, const uint32_t* b) {
    asm volatile(
        "mma.sync.aligned.m16n8k16.row.col.f32.f16.f16.f32 "
        "{%0,%1,%2,%3}, {%4,%5,%6,%7}, {%8,%9}, {%0,%1,%2,%3};\n"
        : "+f"(d[0]), "+f"(d[1]), "+f"(d[2]), "+f"(d[3])
        : "r"(a[0]), "r"(a[1]), "r"(a[2]), "r"(a[3]), "r"(b[0]), "r"(b[1]));
}
__device__ __forceinline__ void ldsm4(uint32_t* r, uint32_t addr) {
    asm volatile("ldmatrix.sync.aligned.m8n8.x4.shared.b16 {%0,%1,%2,%3}, [%4];"
        : "=r"(r[0]), "=r"(r[1]), "=r"(r[2]), "=r"(r[3]) : "r"(addr));
}
__device__ __forceinline__ void ldsm4t(uint32_t* r, uint32_t addr) {
    asm volatile("ldmatrix.sync.aligned.m8n8.x4.trans.shared.b16 {%0,%1,%2,%3}, [%4];"
        : "=r"(r[0]), "=r"(r[1]), "=r"(r[2]), "=r"(r[3]) : "r"(addr));
}
__device__ __forceinline__ void cpa16(uint32_t dst, const void* src) {
    asm volatile("cp.async.cg.shared.global [%0], [%1], 16;" :: "r"(dst), "l"(src));
}
#define CP_COMMIT() asm volatile("cp.async.commit_group;" ::: "memory")
#define CP_WAIT(n)  asm volatile("cp.async.wait_group %0;" :: "n"(n) : "memory")

// ---------------- pre-pass: K, V -> fp16 (rn) ----------------
__global__ void cvt_kv_kernel(const float4* __restrict__ K4, const float4* __restrict__ V4)
{
    int i = blockIdx.x * 256 + threadIdx.x;
    float4 k = K4[i];
    ((uint2*)g_Kh)[i] = make_uint2(h2bits(__floats2half2_rn(k.x, k.y)),
                                   h2bits(__floats2half2_rn(k.z, k.w)));
    float4 v = V4[i];
    ((uint2*)g_Vh)[i] = make_uint2(h2bits(__floats2half2_rn(v.x, v.y)),
                                   h2bits(__floats2half2_rn(v.z, v.w)));
}

// ---------------- single-tensor tile prefetch (64 rows = 1024 x 16B, no commit) ----
__device__ __forceinline__ void prefetch_t(const __half* src, uint32_t buf, int tid)
{
    #pragma unroll
    for (int i = 0; i < 8; i++) {                 // FIXED: full tile (was i<4 = half tile)
        int idx = tid + 128 * i;                  // 1024 chunks of 16B
        int r = idx >> 4, c = idx & 15;
        cpa16(buf + (uint32_t)(r * (KSTRH * 2) + c * 16), src + r * HD + c * 8);
    }
}

// ---------------- QK tile: sacc = Q @ K^T (32 rows x 64 keys per warp) ----------------
__device__ __forceinline__ void qk_tile(float sacc[2][8][4], uint32_t kbu,
                                        uint32_t qbase, uint32_t qbase2)
{
    #pragma unroll
    for (int m = 0; m < 2; m++)
        #pragma unroll
        for (int j = 0; j < 8; j++)
            sacc[m][j][0] = sacc[m][j][1] = sacc[m][j][2] = sacc[m][j][3] = 0.f;

    uint32_t aq[2][2][4];      // [s&1][m][4]
    uint32_t kb[2][2][4];      // [u&1][jj][4]
    ldsm4(aq[0][0], qbase);
    ldsm4(aq[0][1], qbase2);
    ldsm4(kb[0][0], kbu);
    ldsm4(kb[0][1], kbu + 16 * KSTRH * 2);

    #pragma unroll
    for (int u = 0; u < 16; u++) {               // u = 2*s + jph
        const int cur = u & 1, nxt = cur ^ 1;
        if (u < 15) {
            const int un = u + 1, sn = un >> 1, jb = (un & 1) * 2;
            if ((un & 1) == 0) {                 // new s starts at un
                ldsm4(aq[sn & 1][0], qbase + sn * 32);
                ldsm4(aq[sn & 1][1], qbase2 + sn * 32);
            }
            ldsm4(kb[nxt][0], kbu + (jb + 0) * (16 * KSTRH * 2) + sn * 32);
            ldsm4(kb[nxt][1], kbu + (jb + 1) * (16 * KSTRH * 2) + sn * 32);
        }
        const int s = u >> 1, jb = (u & 1) * 2;
        #pragma unroll
        for (int jj = 0; jj < 2; jj++) {
            const int jp = jb + jj;
            mma16(sacc[0][2 * jp],     aq[s & 1][0], kb[cur][jj]);
            mma16(sacc[0][2 * jp + 1], aq[s & 1][0], kb[cur][jj] + 2);
            mma16(sacc[1][2 * jp],     aq[s & 1][1], kb[cur][jj]);
            mma16(sacc[1][2 * jp + 1], aq[s & 1][1], kb[cur][jj] + 2);
        }
    }
}

__global__ __launch_bounds__(128, 2)
void fa15_kernel(const float* __restrict__ Q, float* __restrict__ O)
{
    extern __shared__ __half smh[];
    const int tid  = threadIdx.x;
    const int w    = tid >> 5;       // warp covers rows [32w, 32w+32)
    const int lane = tid & 31;
    const int g    = lane >> 2;
    const int t    = lane & 3;
    const int bh   = blockIdx.y;
    const int q0   = blockIdx.x * BM;

    const uint32_t sb = (uint32_t)__cvta_generic_to_shared(smh);
    const __half* kg = g_Kh + (size_t)bh * SEQ * HD;
    const __half* vg = g_Vh + (size_t)bh * SEQ * HD;

    const uint32_t kbufs[2] = { sb + SM_K0 * 2, sb + SM_K1 * 2 };
    const uint32_t vbufs[2] = { sb + SM_V0 * 2, sb + SM_V1 * 2 };

    // ---- prologue prefetch: group A = {K0, V0}; group B = {K1} ----
    prefetch_t(kg, kbufs[0], tid);
    prefetch_t(vg, vbufs[0], tid);
    CP_COMMIT();
    prefetch_t(kg + BN * HD, kbufs[1], tid);
    CP_COMMIT();

    // ---- Q tile: fp32 gmem -> scale -> fp16 smem (overlaps prefetches) ----
    {
        const float4* gq = (const float4*)(Q + (size_t)bh * SEQ * HD + (size_t)q0 * HD);
        #pragma unroll
        for (int i = 0; i < 32; i++) {
            int idx = tid + 128 * i;              // 4096 float4
            int r = idx >> 5, c = idx & 31;
            float4 v = gq[idx];
            uint2 p = make_uint2(
                h2bits(__floats2half2_rn(v.x * QKSCALE, v.y * QKSCALE)),
                h2bits(__floats2half2_rn(v.z * QKSCALE, v.w * QKSCALE)));
            *(uint2*)(smh + SM_Q + r * QSTRH + c * 4) = p;
        }
    }

    // ---- per-lane ldmatrix base offsets (bytes) ----
    const int qrow = ((lane >> 3) & 1) * 8 + (lane & 7);
    const int qcol = (lane >> 4) * 8;
    const uint32_t qbase = sb + 2u * ((32 * w + qrow) * QSTRH + qcol);
    const uint32_t qbase2 = qbase + 16 * QSTRH * 2;
    const int krow = ((lane >> 4) << 3) + (lane & 7);
    const int kcol = ((lane >> 3) & 1) * 8;
    const uint32_t kboff = 2u * (krow * KSTRH + kcol);
    const int vkey = ((lane >> 3) & 1) * 8 + (lane & 7);
    const int vd   = (lane >> 4) * 8;
    const uint32_t vboff = 2u * (vkey * KSTRH + vd);

    float o[2][16][4];
    #pragma unroll
    for (int m = 0; m < 2; m++)
        #pragma unroll
        for (int j = 0; j < 16; j++)
            o[m][j][0] = o[m][j][1] = o[m][j][2] = o[m][j][3] = 0.f;
    float lp[2][2] = {{0.f, 0.f}, {0.f, 0.f}};

    float sacc[2][8][4];

    // ---- prologue compute: QK(0) (K0 + Q smem ready after wait+barrier) ----
    CP_WAIT(1);          // group A (K0, V0) complete
    __syncthreads();     // + Q smem visible
    qk_tile(sacc, kbufs[0] + kboff, qbase, qbase2);

    for (int tile = 0; tile < NT; tile++) {
        // Top sync: group issued at top of tile-1 -> {K(tile+1), V(tile)} complete.
        // All warps finished QK(tile) (read Kbuf[tile&1]) and PV(tile-1)
        // (read Vbuf[(tile-1)&1]) before this barrier -> both target buffers free.
        CP_WAIT(0);
        __syncthreads();
        {
            bool any = false;
            if (tile + 2 < NT) { prefetch_t(kg + (size_t)(tile + 2) * BN * HD, kbufs[tile & 1], tid); any = true; }
            if (tile + 1 < NT) { prefetch_t(vg + (size_t)(tile + 1) * BN * HD, vbufs[(tile + 1) & 1], tid); any = true; }
            if (any) CP_COMMIT();
        }

        // ---- softmax(tile): pa <- exp2(sacc); sacc input is one iteration old ----
        uint32_t pa[4][2][4];
        __half2 lacc[2][2];
        #pragma unroll
        for (int m = 0; m < 2; m++) {
            lacc[m][0] = __floats2half2_rn(0.f, 0.f);
            lacc[m][1] = __floats2half2_rn(0.f, 0.f);
        }
        #pragma unroll
        for (int s = 0; s < 4; s++) {
            #pragma unroll
            for (int m = 0; m < 2; m++) {
                uint32_t p0 = h2bits(h2exp2(__floats2half2_rn(sacc[m][2 * s][0],     sacc[m][2 * s][1])));
                uint32_t p1 = h2bits(h2exp2(__floats2half2_rn(sacc[m][2 * s][2],     sacc[m][2 * s][3])));
                uint32_t p2 = h2bits(h2exp2(__floats2half2_rn(sacc[m][2 * s + 1][0], sacc[m][2 * s + 1][1])));
                uint32_t p3 = h2bits(h2exp2(__floats2half2_rn(sacc[m][2 * s + 1][2], sacc[m][2 * s + 1][3])));
                pa[s][m][0] = p0; pa[s][m][1] = p1; pa[s][m][2] = p2; pa[s][m][3] = p3;
                lacc[m][0] = __hadd2(lacc[m][0], __hadd2(bitsh2(p0), bitsh2(p2)));  // row g
                lacc[m][1] = __hadd2(lacc[m][1], __hadd2(bitsh2(p1), bitsh2(p3)));  // row g+8
            }
        }
        #pragma unroll
        for (int m = 0; m < 2; m++) {
            float2 fg = __half22float2(lacc[m][0]);
            float2 f8 = __half22float2(lacc[m][1]);
            lp[m][0] += fg.x + fg.y;
            lp[m][1] += f8.x + f8.y;
        }

        // ---- QK(tile+1): overwrites sacc (WAR-safe: softmax above already consumed) ----
        if (tile + 1 < NT)
            qk_tile(sacc, kbufs[(tile + 1) & 1] + kboff, qbase, qbase2);

        // ---- PV(tile): flattened 32-step 2-deep vb pipeline ----
        {
            const uint32_t vbu = vbufs[tile & 1] + vboff;
            uint32_t vb[2][4];
            ldsm4t(vb[0], vbu);
            #pragma unroll
            for (int q = 0; q < 32; q++) {
                const int cur = q & 1, nxt = cur ^ 1;
                if (q < 31) {
                    const int q1 = q + 1;
                    ldsm4t(vb[nxt], vbu + (q1 >> 3) * (16 * KSTRH * 2) + (q1 & 7) * 32);
                }
                const int s = q >> 3, jp2 = q & 7;
                mma16(o[0][2 * jp2],     pa[s][0], vb[cur]);
                mma16(o[0][2 * jp2 + 1], pa[s][0], vb[cur] + 2);
                mma16(o[1][2 * jp2],     pa[s][1], vb[cur]);
                mma16(o[1][2 * jp2 + 1], pa[s][1], vb[cur] + 2);
            }
        }
    }

    // ---- reduce l over t-lanes, scale, store fp32 ----
    #pragma unroll
    for (int m = 0; m < 2; m++)
        #pragma unroll
        for (int h = 0; h < 2; h++) {
            lp[m][h] += __shfl_xor_sync(0xffffffffu, lp[m][h], 1);
            lp[m][h] += __shfl_xor_sync(0xffffffffu, lp[m][h], 2);
        }

    const size_t obase = (size_t)bh * SEQ * HD;
    #pragma unroll
    for (int m = 0; m < 2; m++) {
        const float i0 = 1.f / lp[m][0];
        const float i1 = 1.f / lp[m][1];
        float* om = O + obase + (size_t)(q0 + 32 * w + 16 * m) * HD;
        #pragma unroll
        for (int j2 = 0; j2 < 16; j2++) {
            *(float2*)(om + g * HD + 8 * j2 + 2 * t) =
                make_float2(o[m][j2][0] * i0, o[m][j2][1] * i0);
            *(float2*)(om + (g + 8) * HD + 8 * j2 + 2 * t) =
                make_float2(o[m][j2][2] * i1, o[m][j2][3] * i1);
        }
    }
}

extern "C" void kernel_launch(void* const* d_in, const int* in_sizes, int n_in,
                              void* d_out, int out_size)
{
    const float* Q = (const float*)d_in[0];
    const float* K = (const float*)d_in[1];
    const float* V = (const float*)d_in[2];
    float* O = (float*)d_out;

    cvt_kv_kernel<<<(NBH * SEQ * HD / 4) / 256, 256>>>(
        (const float4*)K, (const float4*)V);

    cudaFuncSetAttribute(fa15_kernel,
                         cudaFuncAttributeMaxDynamicSharedMemorySize, SMEM_BYTES);
    dim3 grid(SEQ / BM, NBH);
    fa15_kernel<<<grid, 128, SMEM_BYTES>>>(Q, O);
}

// round 17
// speedup vs baseline: 1.0320x; 1.0320x over previous
#include <cuda_runtime.h>
#include <cuda_fp16.h>
#include <cstdint>

#define HD 128
#define SEQ 2048
#define NBH 32
#define BM 128
#define BN 64
#define NT (SEQ / BN)            // 32 key tiles
// Q scaled by (1/sqrt(128)) * log2(e) at smem-fill so softmax is exp2(sacc)
#define QKSCALE 0.12751581666519787f

// ---- fp16 scratch for K,V (filled by pre-pass kernel) ----
__device__ __align__(256) __half g_Kh[NBH * SEQ * HD];
__device__ __align__(256) __half g_Vh[NBH * SEQ * HD];

// smem strides in halves; 136 halves = 272B -> ldmatrix banks 4L..4L+3, conflict-free
#define QSTRH 136
#define KSTRH 136
#define KJUMP (16 * KSTRH * 2)   // byte stride between 16-row groups

// smem half-offsets
#define SM_Q  0
#define SM_K0 (BM * QSTRH)
#define SM_K1 (SM_K0 + BN * KSTRH)
#define SM_V0 (SM_K1 + BN * KSTRH)
#define SM_V1 (SM_V0 + BN * KSTRH)
#define SMEM_HALVES (SM_V1 + BN * KSTRH)   // 52224 halves
#define SMEM_BYTES (SMEM_HALVES * 2)       // 104448 B -> 2 CTAs/SM

__device__ __forceinline__ uint32_t h2bits(__half2 h) {
    return *reinterpret_cast<uint32_t*>(&h);
}
__device__ __forceinline__ __half2 bitsh2(uint32_t u) {
    return *reinterpret_cast<__half2*>(&u);
}
__device__ __forceinline__ void mma16(float* d, const uint32_t* a, const uint32_t* b) {
    asm volatile(
        "mma.sync.aligned.m16n8k16.row.col.f32.f16.f16.f32 "
        "{%0,%1,%2,%3}, {%4,%5,%6,%7}, {%8,%9}, {%0,%1,%2,%3};\n"
        : "+f"(d[0]), "+f"(d[1]), "+f"(d[2]), "+f"(d[3])
        : "r"(a[0]), "r"(a[1]), "r"(a[2]), "r"(a[3]), "r"(b[0]), "r"(b[1]));
}
__device__ __forceinline__ void ldsm4(uint32_t* r, uint32_t addr) {
    asm volatile("ldmatrix.sync.aligned.m8n8.x4.shared.b16 {%0,%1,%2,%3}, [%4];"
        : "=r"(r[0]), "=r"(r[1]), "=r"(r[2]), "=r"(r[3]) : "r"(addr));
}
__device__ __forceinline__ void ldsm4t(uint32_t* r, uint32_t addr) {
    asm volatile("ldmatrix.sync.aligned.m8n8.x4.trans.shared.b16 {%0,%1,%2,%3}, [%4];"
        : "=r"(r[0]), "=r"(r[1]), "=r"(r[2]), "=r"(r[3]) : "r"(addr));
}
__device__ __forceinline__ void cpa16(uint32_t dst, const void* src) {
    asm volatile("cp.async.cg.shared.global [%0], [%1], 16;" :: "r"(dst), "l"(src));
}
#define CP_COMMIT() asm volatile("cp.async.commit_group;" ::: "memory")
#define CP_WAIT(n)  asm volatile("cp.async.wait_group %0;" :: "n"(n) : "memory")

// ---------------- pre-pass: K, V -> fp16 (rn) ----------------
__global__ void cvt_kv_kernel(const float4* __restrict__ K4, const float4* __restrict__ V4)
{
    int i = blockIdx.x * 256 + threadIdx.x;
    float4 k = K4[i];
    ((uint2*)g_Kh)[i] = make_uint2(h2bits(__floats2half2_rn(k.x, k.y)),
                                   h2bits(__floats2half2_rn(k.z, k.w)));
    float4 v = V4[i];
    ((uint2*)g_Vh)[i] = make_uint2(h2bits(__floats2half2_rn(v.x, v.y)),
                                   h2bits(__floats2half2_rn(v.z, v.w)));
}

// ---------------- K/V tile prefetch (fp16, cp.async), 128 threads ----------------
__device__ __forceinline__ void prefetch(int bh, int kt, uint32_t kbuf, uint32_t vbuf, int tid)
{
    const __half* kg = g_Kh + (size_t)bh * SEQ * HD + (size_t)kt * BN * HD;
    const __half* vg = g_Vh + (size_t)bh * SEQ * HD + (size_t)kt * BN * HD;
    #pragma unroll
    for (int i = 0; i < 8; i++) {
        int idx = tid + 128 * i;                  // 1024 chunks of 16B per tensor
        int r = idx >> 4, c = idx & 15;
        uint32_t off = (uint32_t)(r * (KSTRH * 2) + c * 16);
        cpa16(kbuf + off, kg + r * HD + c * 8);
        cpa16(vbuf + off, vg + r * HD + c * 8);
    }
    CP_COMMIT();
}

// ---- QK half-tile: sacc = Q @ K^T for 32 keys (jp in {jpbase, jpbase+1}) ----
__device__ __forceinline__ void qk_half(float sacc[2][4][4], uint32_t kbu, int jpbase,
                                        uint32_t qbase, uint32_t qbase2)
{
    #pragma unroll
    for (int m = 0; m < 2; m++)
        #pragma unroll
        for (int j = 0; j < 4; j++)
            sacc[m][j][0] = sacc[m][j][1] = sacc[m][j][2] = sacc[m][j][3] = 0.f;

    const uint32_t kb0 = kbu + (uint32_t)jpbase * KJUMP;
    uint32_t aq[2][2][4];
    uint32_t kb[2][2][4];
    ldsm4(aq[0][0], qbase);
    ldsm4(aq[0][1], qbase2);
    ldsm4(kb[0][0], kb0);
    ldsm4(kb[0][1], kb0 + KJUMP);

    #pragma unroll
    for (int s = 0; s < 8; s++) {
        const int cur = s & 1, nxt = cur ^ 1;
        if (s < 7) {
            ldsm4(aq[nxt][0], qbase + (s + 1) * 32);
            ldsm4(aq[nxt][1], qbase2 + (s + 1) * 32);
            ldsm4(kb[nxt][0], kb0 + (s + 1) * 32);
            ldsm4(kb[nxt][1], kb0 + KJUMP + (s + 1) * 32);
        }
        #pragma unroll
        for (int jj = 0; jj < 2; jj++) {
            mma16(sacc[0][2 * jj],     aq[cur][0], kb[cur][jj]);
            mma16(sacc[0][2 * jj + 1], aq[cur][0], kb[cur][jj] + 2);
            mma16(sacc[1][2 * jj],     aq[cur][1], kb[cur][jj]);
            mma16(sacc[1][2 * jj + 1], aq[cur][1], kb[cur][jj] + 2);
        }
    }
}

// ---- softmax half: pa = exp2(sacc) packed as PV A-frags; lacc accumulates l ----
__device__ __forceinline__ void softmax_half(uint32_t pa[2][2][4], const float sacc[2][4][4],
                                             __half2 lacc[2][2])
{
    #pragma unroll
    for (int sg = 0; sg < 2; sg++) {
        #pragma unroll
        for (int m = 0; m < 2; m++) {
            uint32_t p0 = h2bits(h2exp2(__floats2half2_rn(sacc[m][2 * sg][0],     sacc[m][2 * sg][1])));
            uint32_t p1 = h2bits(h2exp2(__floats2half2_rn(sacc[m][2 * sg][2],     sacc[m][2 * sg][3])));
            uint32_t p2 = h2bits(h2exp2(__floats2half2_rn(sacc[m][2 * sg + 1][0], sacc[m][2 * sg + 1][1])));
            uint32_t p3 = h2bits(h2exp2(__floats2half2_rn(sacc[m][2 * sg + 1][2], sacc[m][2 * sg + 1][3])));
            pa[sg][m][0] = p0; pa[sg][m][1] = p1; pa[sg][m][2] = p2; pa[sg][m][3] = p3;
            lacc[m][0] = __hadd2(lacc[m][0], __hadd2(bitsh2(p0), bitsh2(p2)));  // row g
            lacc[m][1] = __hadd2(lacc[m][1], __hadd2(bitsh2(p1), bitsh2(p3)));  // row g+8
        }
    }
}

// ---- PV half: o += P(32 keys) @ V; vb 2-deep pipeline over 16 steps ----
__device__ __forceinline__ void pv_half(float o[2][16][4], const uint32_t pa[2][2][4],
                                        uint32_t vbu, int sgbase)
{
    const uint32_t vb0 = vbu + (uint32_t)sgbase * KJUMP;
    uint32_t vb[2][4];
    ldsm4t(vb[0], vb0);
    #pragma unroll
    for (int q = 0; q < 16; q++) {
        const int cur = q & 1, nxt = cur ^ 1;
        if (q < 15) {
            const int q1 = q + 1;
            ldsm4t(vb[nxt], vb0 + (q1 >> 3) * KJUMP + (q1 & 7) * 32);
        }
        const int sg = q >> 3, jp2 = q & 7;
        mma16(o[0][2 * jp2],     pa[sg][0], vb[cur]);
        mma16(o[0][2 * jp2 + 1], pa[sg][0], vb[cur] + 2);
        mma16(o[1][2 * jp2],     pa[sg][1], vb[cur]);
        mma16(o[1][2 * jp2 + 1], pa[sg][1], vb[cur] + 2);
    }
}

__global__ __launch_bounds__(128, 2)
void fa17_kernel(const float* __restrict__ Q, float* __restrict__ O)
{
    extern __shared__ __half smh[];
    const int tid  = threadIdx.x;
    const int w    = tid >> 5;       // warp covers rows [32w, 32w+32)
    const int lane = tid & 31;
    const int g    = lane >> 2;
    const int t    = lane & 3;
    const int bh   = blockIdx.y;
    const int q0   = blockIdx.x * BM;

    const uint32_t sb = (uint32_t)__cvta_generic_to_shared(smh);

    // ---- prefetch tile0 (distance-1 pipeline) ----
    prefetch(bh, 0, sb + SM_K0 * 2, sb + SM_V0 * 2, tid);

    // ---- Q tile: fp32 gmem -> scale -> fp16 smem (overlaps tile0 cp.async) ----
    {
        const float4* gq = (const float4*)(Q + (size_t)bh * SEQ * HD + (size_t)q0 * HD);
        #pragma unroll
        for (int i = 0; i < 32; i++) {
            int idx = tid + 128 * i;              // 4096 float4
            int r = idx >> 5, c = idx & 31;
            float4 v = gq[idx];
            uint2 p = make_uint2(
                h2bits(__floats2half2_rn(v.x * QKSCALE, v.y * QKSCALE)),
                h2bits(__floats2half2_rn(v.z * QKSCALE, v.w * QKSCALE)));
            *(uint2*)(smh + SM_Q + r * QSTRH + c * 4) = p;
        }
    }

    // ---- per-lane ldmatrix base offsets (bytes) ----
    const int qrow = ((lane >> 3) & 1) * 8 + (lane & 7);
    const int qcol = (lane >> 4) * 8;
    const uint32_t qbase = sb + 2u * ((32 * w + qrow) * QSTRH + qcol);
    const uint32_t qbase2 = qbase + 16 * QSTRH * 2;
    const int krow = ((lane >> 4) << 3) + (lane & 7);
    const int kcol = ((lane >> 3) & 1) * 8;
    const uint32_t kboff = 2u * (krow * KSTRH + kcol);
    const int vkey = ((lane >> 3) & 1) * 8 + (lane & 7);
    const int vd   = (lane >> 4) * 8;
    const uint32_t vboff = 2u * (vkey * KSTRH + vd);

    float o[2][16][4];
    #pragma unroll
    for (int m = 0; m < 2; m++)
        #pragma unroll
        for (int j = 0; j < 16; j++)
            o[m][j][0] = o[m][j][1] = o[m][j][2] = o[m][j][3] = 0.f;
    float lp[2][2] = {{0.f, 0.f}, {0.f, 0.f}};

    for (int tile = 0; tile < NT; tile++) {
        CP_WAIT(0);
        __syncthreads();
        // Buffer (tile+1)&1 was last read in tile-1; all warps passed the barrier.
        if (tile + 1 < NT) {
            prefetch(bh, tile + 1,
                     sb + 2u * (((tile + 1) & 1) ? SM_K1 : SM_K0),
                     sb + 2u * (((tile + 1) & 1) ? SM_V1 : SM_V0), tid);
        }

        const uint32_t kbu = sb + 2u * ((tile & 1) ? SM_K1 : SM_K0) + kboff;
        const uint32_t vbu = sb + 2u * ((tile & 1) ? SM_V1 : SM_V0) + vboff;

        __half2 lacc[2][2];
        #pragma unroll
        for (int m = 0; m < 2; m++) {
            lacc[m][0] = __floats2half2_rn(0.f, 0.f);
            lacc[m][1] = __floats2half2_rn(0.f, 0.f);
        }

        // ---- half-key stagger: QK_A, [softmax_A ∥ QK_B], PV_A, [softmax_B ∥ ...], PV_B
        float sacc[2][4][4];
        uint32_t paA[2][2][4], paB[2][2][4];

        qk_half(sacc, kbu, 0, qbase, qbase2);          // keys 0-31 -> sacc (final)
        softmax_half(paA, sacc, lacc);                 // indep of QK_B -> interleaved
        qk_half(sacc, kbu, 2, qbase, qbase2);          // keys 32-63 (sacc reused)
        pv_half(o, paA, vbu, 0);                       // paA ready long ago
        softmax_half(paB, sacc, lacc);                 // sacc final since QK_B end
        pv_half(o, paB, vbu, 2);

        // fold this tile's f16 partial sums into f32 totals
        #pragma unroll
        for (int m = 0; m < 2; m++) {
            float2 fg = __half22float2(lacc[m][0]);
            float2 f8 = __half22float2(lacc[m][1]);
            lp[m][0] += fg.x + fg.y;
            lp[m][1] += f8.x + f8.y;
        }
    }

    // ---- reduce l over t-lanes, scale, store fp32 ----
    #pragma unroll
    for (int m = 0; m < 2; m++)
        #pragma unroll
        for (int h = 0; h < 2; h++) {
            lp[m][h] += __shfl_xor_sync(0xffffffffu, lp[m][h], 1);
            lp[m][h] += __shfl_xor_sync(0xffffffffu, lp[m][h], 2);
        }

    const size_t obase = (size_t)bh * SEQ * HD;
    #pragma unroll
    for (int m = 0; m < 2; m++) {
        const float i0 = 1.f / lp[m][0];
        const float i1 = 1.f / lp[m][1];
        float* om = O + obase + (size_t)(q0 + 32 * w + 16 * m) * HD;
        #pragma unroll
        for (int j2 = 0; j2 < 16; j2++) {
            *(float2*)(om + g * HD + 8 * j2 + 2 * t) =
                make_float2(o[m][j2][0] * i0, o[m][j2][1] * i0);
            *(float2*)(om + (g + 8) * HD + 8 * j2 + 2 * t) =
                make_float2(o[m][j2][2] * i1, o[m][j2][3] * i1);
        }
    }
}

extern "C" void kernel_launch(void* const* d_in, const int* in_sizes, int n_in,
                              void* d_out, int out_size)
{
    const float* Q = (const float*)d_in[0];
    const float* K = (const float*)d_in[1];
    const float* V = (const float*)d_in[2];
    float* O = (float*)d_out;

    cvt_kv_kernel<<<(NBH * SEQ * HD / 4) / 256, 256>>>(
        (const float4*)K, (const float4*)V);

    cudaFuncSetAttribute(fa17_kernel,
                         cudaFuncAttributeMaxDynamicSharedMemorySize, SMEM_BYTES);
    dim3 grid(SEQ / BM, NBH);
    fa17_kernel<<<grid, 128, SMEM_BYTES>>>(Q, O);
}